// round 11
// baseline (speedup 1.0000x reference)
#include <cuda_runtime.h>
#include <math.h>

constexpr int NN = 50000;   // nodes
constexpr int HH = 16;      // hidden
constexpr int RR = 32;      // relations
constexpr int CC = 8;       // classes
constexpr int RN = RR * NN; // segments
constexpr int EMAX = 1600000;

// Scratch (device globals: no allocation allowed)
__device__ int                g_cnt[RN];     // edge counts per (rel,dst)
__device__ float              g_x[NN * HH];  // layer-1 node features
__device__ unsigned long long g_pk[EMAX + 1];// packed edges (sorted by rel): s | d<<16 | r<<32
__device__ int                g_hist[RR];    // global relation histogram (zeroed by k_scan)
__device__ int                g_cursor[RR];  // scatter cursors (= exclusive scan of hist)

// ---------------------------------------------------------------------------
// 0) zero scratch + output, fused with relation histogram over et
__global__ void k_init_hist(const int* __restrict__ et, float* __restrict__ out, int E) {
    __shared__ int sh[RR];
    int t = threadIdx.x;
    if (t < RR) sh[t] = 0;
    __syncthreads();
    int i = blockIdx.x * blockDim.x + t;
    if (i < RN)      g_cnt[i] = 0;
    if (i < NN * HH) g_x[i]   = 0.0f;
    if (i < NN * CC) out[i]   = 0.0f;
    if (i < E)       atomicAdd(&sh[et[i]], 1);
    __syncthreads();
    if (t < RR) {
        int v = sh[t];
        if (v) atomicAdd(&g_hist[t], v);
    }
}

// 1) exclusive scan of 32-bin histogram -> cursors; re-zero g_hist for next replay
__global__ void k_scan() {
    __shared__ int s[RR];
    int t = threadIdx.x;
    s[t] = g_hist[t];
    __syncthreads();
    if (t == 0) {
        int acc = 0;
        for (int i = 0; i < RR; i++) { int v = s[i]; s[i] = acc; acc += v; }
    }
    __syncthreads();
    g_cursor[t] = s[t];
    g_hist[t] = 0;
}

// 2) scatter edges into relation-sorted packed array (warp-aggregated ranks)
//    + fused (rel,dst) segment counting
__global__ void k_scatter(const int* __restrict__ et, const int* __restrict__ srcv,
                          const int* __restrict__ dstv, int E) {
    __shared__ int sh[RR];     // per-block bin sizes / ranks
    __shared__ int sbase[RR];  // per-block bin bases
    int t = threadIdx.x;
    if (t < RR) sh[t] = 0;
    __syncthreads();

    int e = blockIdx.x * blockDim.x + t;
    bool ok = e < E;
    int r = ok ? et[e] : RR;               // RR = dummy bin for tail lanes
    int s = 0, d = 0;
    if (ok) { s = srcv[e]; d = dstv[e]; }

    // warp-aggregated rank within block bin
    unsigned m = __match_any_sync(0xffffffffu, r);
    int lane = t & 31;
    int leader = __ffs(m) - 1;
    int pre = __popc(m & ((1u << lane) - 1));
    int base = 0;
    if (lane == leader && r < RR) base = atomicAdd(&sh[r], __popc(m));
    base = __shfl_sync(0xffffffffu, base, leader);
    int rank = base + pre;

    __syncthreads();
    if (t < RR) sbase[t] = sh[t] ? atomicAdd(&g_cursor[t], sh[t]) : 0;
    __syncthreads();

    if (ok) {
        g_pk[sbase[r] + rank] = (unsigned long long)(unsigned)s
                              | ((unsigned long long)(unsigned)d << 16)
                              | ((unsigned long long)(unsigned)r << 32);
        atomicAdd(&g_cnt[r * NN + d], 1);
    }
}

// 3) layer-1 scatter: x[d] += (1/cnt[r,d]) * w1[r,s]
//    2 edges per thread-group via ulonglong2; 4 threads per edge, float4 each.
__global__ void k_l1(const float* __restrict__ w1, int E) {
    int idx = blockIdx.x * blockDim.x + threadIdx.x;
    int g = idx >> 2, q = idx & 3;
    int e0 = 2 * g;
    if (e0 >= E) return;
    bool ok1 = (e0 + 1) < E;

    ulonglong2 pv = __ldg(((const ulonglong2*)g_pk) + g);
    unsigned long long p0 = pv.x, p1 = pv.y;

    int s0 = (int)(p0 & 0xFFFFu), d0 = (int)((p0 >> 16) & 0xFFFFu), r0 = (int)(p0 >> 32);
    int s1 = (int)(p1 & 0xFFFFu), d1 = (int)((p1 >> 16) & 0xFFFFu), r1 = (int)(p1 >> 32);

    int c0 = __ldg(&g_cnt[r0 * NN + d0]);
    int c1 = ok1 ? __ldg(&g_cnt[r1 * NN + d1]) : 1;
    const float4 w0 = __ldg(((const float4*)(w1 + ((long)(r0 * NN + s0) << 4))) + q);
    float4 w1v = make_float4(0.f, 0.f, 0.f, 0.f);
    if (ok1) w1v = __ldg(((const float4*)(w1 + ((long)(r1 * NN + s1) << 4))) + q);

    float i0 = __fdividef(1.0f, (float)c0);
    float i1 = __fdividef(1.0f, (float)c1);

    float* pd0 = &g_x[d0 * HH + q * 4];
    asm volatile("red.global.add.v4.f32 [%0], {%1,%2,%3,%4};"
                 :: "l"(pd0), "f"(w0.x * i0), "f"(w0.y * i0),
                    "f"(w0.z * i0), "f"(w0.w * i0) : "memory");
    if (ok1) {
        float* pd1 = &g_x[d1 * HH + q * 4];
        asm volatile("red.global.add.v4.f32 [%0], {%1,%2,%3,%4};"
                     :: "l"(pd1), "f"(w1v.x * i1), "f"(w1v.y * i1),
                        "f"(w1v.z * i1), "f"(w1v.w * i1) : "memory");
    }
}

// 4) x = relu(x + root1 + b1)  (float4)
__global__ void k_relu(const float4* __restrict__ root1, const float* __restrict__ b1) {
    int i = blockIdx.x * blockDim.x + threadIdx.x;
    if (i >= NN * HH / 4) return;
    float4 v = ((float4*)g_x)[i];
    float4 rr = __ldg(root1 + i);
    int q = (i & 3) * 4;
    v.x += rr.x + b1[q];
    v.y += rr.y + b1[q + 1];
    v.z += rr.z + b1[q + 2];
    v.w += rr.w + b1[q + 3];
    v.x = fmaxf(v.x, 0.f); v.y = fmaxf(v.y, 0.f);
    v.z = fmaxf(v.z, 0.f); v.w = fmaxf(v.w, 0.f);
    ((float4*)g_x)[i] = v;
}

// 5) layer-2 scatter: out[d] += (1/cnt[r,d]) * (x[s] @ w2[r])
//    2 edges per thread per iteration (ulonglong2); r-sorted -> broadcast smem reads
__global__ void __launch_bounds__(256) k_l2(const float* __restrict__ w2,
                                            float* __restrict__ out, int E) {
    __shared__ float s_w2[RR * HH * CC];   // 16 KB
    for (int i = threadIdx.x; i < RR * HH * CC; i += blockDim.x) s_w2[i] = w2[i];
    __syncthreads();

    int P = (E + 1) >> 1;   // edge pairs
    int stride = gridDim.x * blockDim.x;
    for (int g = blockIdx.x * blockDim.x + threadIdx.x; g < P; g += stride) {
        ulonglong2 pv = __ldg(((const ulonglong2*)g_pk) + g);
        unsigned long long p0 = pv.x, p1 = pv.y;
        int e1ok = (2 * g + 1) < E;

        int s0 = (int)(p0 & 0xFFFFu), d0 = (int)((p0 >> 16) & 0xFFFFu), r0 = (int)(p0 >> 32);
        int s1 = (int)(p1 & 0xFFFFu), d1 = (int)((p1 >> 16) & 0xFFFFu), r1 = (int)(p1 >> 32);

        int c0 = __ldg(&g_cnt[r0 * NN + d0]);
        int c1 = e1ok ? __ldg(&g_cnt[r1 * NN + d1]) : 1;
        float i0 = __fdividef(1.0f, (float)c0);
        float i1 = __fdividef(1.0f, (float)c1);

        const float4* xr0 = (const float4*)(g_x + s0 * HH);
        const float4* xr1 = (const float4*)(g_x + s1 * HH);
        float4 a0 = __ldg(xr0), a1 = __ldg(xr0 + 1), a2 = __ldg(xr0 + 2), a3 = __ldg(xr0 + 3);
        float4 b0, b1, b2, b3;
        if (e1ok) { b0 = __ldg(xr1); b1 = __ldg(xr1 + 1); b2 = __ldg(xr1 + 2); b3 = __ldg(xr1 + 3); }
        else      { b0 = b1 = b2 = b3 = make_float4(0.f, 0.f, 0.f, 0.f); }

        float xa[16] = {a0.x, a0.y, a0.z, a0.w, a1.x, a1.y, a1.z, a1.w,
                        a2.x, a2.y, a2.z, a2.w, a3.x, a3.y, a3.z, a3.w};
        float xb[16] = {b0.x, b0.y, b0.z, b0.w, b1.x, b1.y, b1.z, b1.w,
                        b2.x, b2.y, b2.z, b2.w, b3.x, b3.y, b3.z, b3.w};

        const float* wr0 = s_w2 + r0 * HH * CC;
        const float* wr1 = s_w2 + r1 * HH * CC;
        float y0[CC] = {0,0,0,0,0,0,0,0};
        float y1[CC] = {0,0,0,0,0,0,0,0};
#pragma unroll
        for (int h = 0; h < HH; h++) {
            float va = xa[h], vb = xb[h];
#pragma unroll
            for (int c = 0; c < CC; c++) {
                y0[c] += va * wr0[h * CC + c];
                y1[c] += vb * wr1[h * CC + c];
            }
        }
        float* pd0 = out + d0 * CC;
        asm volatile("red.global.add.v4.f32 [%0], {%1,%2,%3,%4};"
                     :: "l"(pd0), "f"(y0[0] * i0), "f"(y0[1] * i0),
                        "f"(y0[2] * i0), "f"(y0[3] * i0) : "memory");
        asm volatile("red.global.add.v4.f32 [%0], {%1,%2,%3,%4};"
                     :: "l"(pd0 + 4), "f"(y0[4] * i0), "f"(y0[5] * i0),
                        "f"(y0[6] * i0), "f"(y0[7] * i0) : "memory");
        if (e1ok) {
            float* pd1 = out + d1 * CC;
            asm volatile("red.global.add.v4.f32 [%0], {%1,%2,%3,%4};"
                         :: "l"(pd1), "f"(y1[0] * i1), "f"(y1[1] * i1),
                            "f"(y1[2] * i1), "f"(y1[3] * i1) : "memory");
            asm volatile("red.global.add.v4.f32 [%0], {%1,%2,%3,%4};"
                         :: "l"(pd1 + 4), "f"(y1[4] * i1), "f"(y1[5] * i1),
                            "f"(y1[6] * i1), "f"(y1[7] * i1) : "memory");
        }
    }
}

// 6) finalize: out = log_softmax(out + x @ root2 + b2)
__global__ void k_fin(const float* __restrict__ root2, const float* __restrict__ b2,
                      float* __restrict__ out) {
    __shared__ float s_r2[HH * CC];
    __shared__ float s_b2[CC];
    for (int i = threadIdx.x; i < HH * CC; i += blockDim.x) s_r2[i] = root2[i];
    if (threadIdx.x < CC) s_b2[threadIdx.x] = b2[threadIdx.x];
    __syncthreads();

    int n = blockIdx.x * blockDim.x + threadIdx.x;
    if (n >= NN) return;

    float y[CC];
    float4 a0 = *(const float4*)(out + n * CC);
    float4 a1 = *(const float4*)(out + n * CC + 4);
    y[0] = a0.x; y[1] = a0.y; y[2] = a0.z; y[3] = a0.w;
    y[4] = a1.x; y[5] = a1.y; y[6] = a1.z; y[7] = a1.w;

#pragma unroll
    for (int h = 0; h < HH; h++) {
        float xv = g_x[n * HH + h];
#pragma unroll
        for (int c = 0; c < CC; c++) y[c] += xv * s_r2[h * CC + c];
    }
#pragma unroll
    for (int c = 0; c < CC; c++) y[c] += s_b2[c];

    float m = y[0];
#pragma unroll
    for (int c = 1; c < CC; c++) m = fmaxf(m, y[c]);
    float sum = 0.0f;
#pragma unroll
    for (int c = 0; c < CC; c++) sum += __expf(y[c] - m);
    float l = m + logf(sum);
#pragma unroll
    for (int c = 0; c < CC; c++) out[n * CC + c] = y[c] - l;
}

// ---------------------------------------------------------------------------
extern "C" void kernel_launch(void* const* d_in, const int* in_sizes, int n_in,
                              void* d_out, int out_size) {
    const int*   ei    = (const int*)d_in[0];     // [2, E]
    const int*   et    = (const int*)d_in[1];     // [E]
    const float* w1    = (const float*)d_in[2];   // [R, N, H]
    const float* root1 = (const float*)d_in[3];   // [N, H]
    const float* b1    = (const float*)d_in[4];   // [H]
    const float* w2    = (const float*)d_in[5];   // [R, H, C]
    const float* root2 = (const float*)d_in[6];   // [H, C]
    const float* b2    = (const float*)d_in[7];   // [C]
    float* out = (float*)d_out;

    const int E = in_sizes[0] / 2;
    const int* srcv = ei;
    const int* dstv = ei + E;

    const int T = 256;
    int big = (RN > E ? RN : E);
    k_init_hist <<<(big + T - 1) / T, T>>> (et, out, E);
    k_scan      <<<1, RR>>> ();
    k_scatter   <<<(E + T - 1) / T, T>>> (et, srcv, dstv, E);
    int pairs = (E + 1) / 2;
    k_l1        <<<(4 * pairs + T - 1) / T, T>>> (w1, E);
    k_relu      <<<(NN * HH / 4 + T - 1) / T, T>>> ((const float4*)root1, b1);
    k_l2        <<<1184, T>>> (w2, out, E);
    k_fin       <<<(NN + T - 1) / T, T>>> (root2, b2, out);
}